// round 1
// baseline (speedup 1.0000x reference)
#include <cuda_runtime.h>

#define NN 200000   // nodes
#define NE 640000   // edges
#define DN 128      // node features
#define DE 32       // edge features
#define H  128      // hidden
#define KE 160      // DN + DE  (edge-GEMM K)
#define KN 256      // DN + H   (node-GEMM K)

#define TE 16       // edges per block (edge kernel)
#define TN 16       // nodes per block (node kernel)

// Scratch (allocation-free): agg accumulator + normalized int32 indices
__device__ float g_agg[(size_t)NN * H];
__device__ int   g_row[NE];
__device__ int   g_col[NE];

// ---------------------------------------------------------------------------
// prep: detect edge_index width (int64 vs int32), normalize to int32,
//       and zero the agg scratch. Grid-stride; every block independently
//       computes the (uniform, deterministic) width flag.
// ---------------------------------------------------------------------------
__global__ void prep_kernel(const unsigned int* __restrict__ eraw)
{
    // int64 little-endian layout: [lo0, hi0, lo1, hi1, ...] with hi == 0
    // (indices are in [0, 200000)). For int32 the odd words are real random
    // indices, so "all 32 odd words zero" only happens for int64.
    bool is64 = true;
    for (int i = 1; i < 64; i += 2)
        if (eraw[i] != 0u) { is64 = false; break; }

    int tid    = blockIdx.x * blockDim.x + threadIdx.x;
    int stride = gridDim.x * blockDim.x;

    if (is64) {
        const long long* p = (const long long*)eraw;
        for (int e = tid; e < NE; e += stride) {
            g_row[e] = (int)p[e];
            g_col[e] = (int)p[NE + e];
        }
    } else {
        const int* p = (const int*)eraw;
        for (int e = tid; e < NE; e += stride) {
            g_row[e] = p[e];
            g_col[e] = p[NE + e];
        }
    }

    float4  z = make_float4(0.f, 0.f, 0.f, 0.f);
    float4* a = (float4*)g_agg;
    const int nvec = NN * H / 4;
    for (int i = tid; i < nvec; i += stride) a[i] = z;
}

// ---------------------------------------------------------------------------
// edge kernel: msg[e] = concat(x[row[e]], edge_attr[e]) @ W1 + b1
//              atomicAdd into g_agg[col[e]]
// 128 threads, each owns one output column; TE=16 edges staged in SMEM.
// ---------------------------------------------------------------------------
__global__ __launch_bounds__(128) void edge_kernel(
    const float* __restrict__ x,
    const float* __restrict__ ea,
    const float* __restrict__ W1,
    const float* __restrict__ b1)
{
    __shared__ float s_in[TE][KE];   // 16 x 160 x 4B = 10 KB
    __shared__ int   s_src[TE];
    __shared__ int   s_dst[TE];

    const int tid = threadIdx.x;
    const int e0  = blockIdx.x * TE;

    if (tid < TE) {
        s_src[tid] = g_row[e0 + tid];
        s_dst[tid] = g_col[e0 + tid];
    }
    __syncthreads();

    // Stage gathered inputs: TE * (KE/4) = 640 float4 loads
    for (int idx = tid; idx < TE * (KE / 4); idx += 128) {
        int e = idx / (KE / 4);
        int q = idx - e * (KE / 4);
        float4 v;
        if (q < DN / 4)
            v = ((const float4*)(x + (size_t)s_src[e] * DN))[q];
        else
            v = ((const float4*)(ea + (size_t)(e0 + e) * DE))[q - DN / 4];
        *(float4*)&s_in[e][q * 4] = v;
    }
    __syncthreads();

    const int col = tid;
    const float bv = b1[col];
    float acc[TE];
#pragma unroll
    for (int e = 0; e < TE; e++) acc[e] = bv;

#pragma unroll 4
    for (int kk = 0; kk < KE / 4; kk++) {
        const float* wp = W1 + (size_t)kk * 4 * H + col;
        float w0 = wp[0 * H];
        float w1 = wp[1 * H];
        float w2 = wp[2 * H];
        float w3 = wp[3 * H];
#pragma unroll
        for (int e = 0; e < TE; e++) {
            float4 v = *(const float4*)&s_in[e][kk * 4];
            acc[e] = fmaf(v.x, w0, acc[e]);
            acc[e] = fmaf(v.y, w1, acc[e]);
            acc[e] = fmaf(v.z, w2, acc[e]);
            acc[e] = fmaf(v.w, w3, acc[e]);
        }
    }

#pragma unroll
    for (int e = 0; e < TE; e++)
        atomicAdd(&g_agg[(size_t)s_dst[e] * H + col], acc[e]);
}

// ---------------------------------------------------------------------------
// node kernel: out[n] = concat(x[n], agg[n]) @ W2 + b2
// ---------------------------------------------------------------------------
__global__ __launch_bounds__(128) void node_kernel(
    const float* __restrict__ x,
    const float* __restrict__ W2,
    const float* __restrict__ b2,
    float* __restrict__ out)
{
    __shared__ float s_in[TN][KN];   // 16 x 256 x 4B = 16 KB

    const int tid = threadIdx.x;
    const int n0  = blockIdx.x * TN;

    // Stage inputs: fully coalesced (x and agg are row-contiguous per node)
    for (int idx = tid; idx < TN * (KN / 4); idx += 128) {
        int n = idx >> 6;        // KN/4 = 64
        int q = idx & 63;
        float4 v;
        if (q < DN / 4)
            v = ((const float4*)(x + (size_t)(n0 + n) * DN))[q];
        else
            v = ((const float4*)(g_agg + (size_t)(n0 + n) * H))[q - DN / 4];
        *(float4*)&s_in[n][q * 4] = v;
    }
    __syncthreads();

    const int col = tid;
    const float bv = b2[col];
    float acc[TN];
#pragma unroll
    for (int n = 0; n < TN; n++) acc[n] = bv;

#pragma unroll 4
    for (int kk = 0; kk < KN / 4; kk++) {
        const float* wp = W2 + (size_t)kk * 4 * H + col;
        float w0 = wp[0 * H];
        float w1 = wp[1 * H];
        float w2 = wp[2 * H];
        float w3 = wp[3 * H];
#pragma unroll
        for (int n = 0; n < TN; n++) {
            float4 v = *(const float4*)&s_in[n][kk * 4];
            acc[n] = fmaf(v.x, w0, acc[n]);
            acc[n] = fmaf(v.y, w1, acc[n]);
            acc[n] = fmaf(v.z, w2, acc[n]);
            acc[n] = fmaf(v.w, w3, acc[n]);
        }
    }

#pragma unroll
    for (int n = 0; n < TN; n++)
        out[(size_t)(n0 + n) * H + col] = acc[n];
}

// ---------------------------------------------------------------------------
// launch: prep -> edge -> node (stream order provides dependencies)
// inputs: 0=x 1=edge_index 2=edge_attr 3=u(unused) 4=batch(unused)
//         5=W1 6=b1 7=W2 8=b2
// ---------------------------------------------------------------------------
extern "C" void kernel_launch(void* const* d_in, const int* in_sizes, int n_in,
                              void* d_out, int out_size)
{
    const float*        x    = (const float*)d_in[0];
    const unsigned int* eraw = (const unsigned int*)d_in[1];
    const float*        ea   = (const float*)d_in[2];
    const float*        W1   = (const float*)d_in[5];
    const float*        b1   = (const float*)d_in[6];
    const float*        W2   = (const float*)d_in[7];
    const float*        b2   = (const float*)d_in[8];

    prep_kernel<<<2048, 256>>>(eraw);
    edge_kernel<<<NE / TE, 128>>>(x, ea, W1, b1);
    node_kernel<<<NN / TN, 128>>>(x, W2, b2, (float*)d_out);
}

// round 4
// speedup vs baseline: 1.6458x; 1.6458x over previous
#include <cuda_runtime.h>
#include <cuda_bf16.h>
#include <cstdint>

#define NN 200000
#define NE 640000
#define DN 128
#define DE 32
#define H  128
#define KE 160      // edge K
#define KN 256      // node K
#define NSM 148

#define EDGE_TILES (NE / 128)   // 5000, exact
#define NODE_TILES (NN / 64)    // 3125, exact

// padded SMEM strides (bytes). (stride mod 128)/16 odd multiples -> conflict-free ldmatrix
#define EB_STRIDE 272           // B rows: 128 bf16 + 8 pad
#define EA_STRIDE 336           // edge A rows: 160 bf16 + 8 pad
#define NA_STRIDE 528           // node A rows: 256 bf16 + 8 pad

// edge dynamic smem layout
#define EA_HI 0
#define EA_LO (128 * EA_STRIDE)                 // 43008
#define EB_HI (2 * 128 * EA_STRIDE)             // 86016
#define EB_LO (EB_HI + KE * EB_STRIDE)          // 129536
#define EDGE_SMEM (EB_LO + KE * EB_STRIDE)      // 173056 (~169 KB)

// node dynamic smem layout
#define NA_HI 0
#define NA_LO (64 * NA_STRIDE)                  // 33792
#define NB_HI (2 * 64 * NA_STRIDE)              // 67584
#define NB_LO (NB_HI + KN * EB_STRIDE)          // 137216
#define NODE_SMEM (NB_LO + KN * EB_STRIDE)      // 206848 (~202 KB)

__device__ __align__(256) float g_agg[(size_t)NN * H];
__device__ int g_row[NE];
__device__ int g_col[NE];

// ---------------------------------------------------------------------------
// helpers
// ---------------------------------------------------------------------------
__device__ __forceinline__ uint32_t smem_u32(const void* p) {
    uint32_t a;
    asm("{ .reg .u64 t; cvta.to.shared.u64 t, %1; cvt.u32.u64 %0, t; }"
        : "=r"(a) : "l"(p));
    return a;
}
// pack two floats to bf16x2 (v0 -> low half, v1 -> high half)
__device__ __forceinline__ uint32_t pack_bf16(float v0, float v1) {
    uint32_t r;
    asm("cvt.rn.bf16x2.f32 %0, %1, %2;" : "=r"(r) : "f"(v1), "f"(v0));
    return r;
}
// split float4 -> packed hi pair + lo (residual) pair
__device__ __forceinline__ void split4(float4 v, uint32_t* hi, uint32_t* lo) {
    uint32_t h01 = pack_bf16(v.x, v.y);
    uint32_t h23 = pack_bf16(v.z, v.w);
    float r0 = v.x - __uint_as_float(h01 << 16);
    float r1 = v.y - __uint_as_float(h01 & 0xFFFF0000u);
    float r2 = v.z - __uint_as_float(h23 << 16);
    float r3 = v.w - __uint_as_float(h23 & 0xFFFF0000u);
    hi[0] = h01; hi[1] = h23;
    lo[0] = pack_bf16(r0, r1);
    lo[1] = pack_bf16(r2, r3);
}
__device__ __forceinline__ void ldsm_x4(uint32_t* r, uint32_t a) {
    asm volatile("ldmatrix.sync.aligned.m8n8.x4.shared.b16 {%0,%1,%2,%3}, [%4];"
                 : "=r"(r[0]), "=r"(r[1]), "=r"(r[2]), "=r"(r[3]) : "r"(a));
}
__device__ __forceinline__ void ldsm_x4t(uint32_t* r, uint32_t a) {
    asm volatile("ldmatrix.sync.aligned.m8n8.x4.trans.shared.b16 {%0,%1,%2,%3}, [%4];"
                 : "=r"(r[0]), "=r"(r[1]), "=r"(r[2]), "=r"(r[3]) : "r"(a));
}
__device__ __forceinline__ void mma_bf16(float* c, const uint32_t* a,
                                         uint32_t b0, uint32_t b1) {
    asm volatile(
        "mma.sync.aligned.m16n8k16.row.col.f32.bf16.bf16.f32 "
        "{%0,%1,%2,%3}, {%4,%5,%6,%7}, {%8,%9}, {%0,%1,%2,%3};"
        : "+f"(c[0]), "+f"(c[1]), "+f"(c[2]), "+f"(c[3])
        : "r"(a[0]), "r"(a[1]), "r"(a[2]), "r"(a[3]), "r"(b0), "r"(b1));
}
__device__ __forceinline__ void red_add_v2(float* p, float a, float b) {
    asm volatile("red.global.add.v2.f32 [%0], {%1,%2};"
                 :: "l"(p), "f"(a), "f"(b) : "memory");
}

// stage a weight matrix [K][128] fp32 -> smem hi/lo bf16 rows (stride EB_STRIDE)
__device__ __forceinline__ void stage_B(const float* __restrict__ W, int K,
                                        char* bhi, char* blo, int tid, int nthr) {
    for (int idx = tid; idx < K * 128; idx += nthr) {
        int k = idx >> 7, n = idx & 127;
        float v = W[idx];
        __nv_bfloat16 h = __float2bfloat16_rn(v);
        float r = v - __bfloat162float(h);
        *(__nv_bfloat16*)(bhi + k * EB_STRIDE + n * 2) = h;
        *(__nv_bfloat16*)(blo + k * EB_STRIDE + n * 2) = __float2bfloat16_rn(r);
    }
}

// ---------------------------------------------------------------------------
// prep: detect int64 vs int32 edge_index, normalize to int32, zero agg
// ---------------------------------------------------------------------------
__global__ void prep_kernel(const unsigned int* __restrict__ eraw)
{
    bool is64 = true;
    for (int i = 1; i < 64; i += 2)
        if (eraw[i] != 0u) { is64 = false; break; }

    int tid = blockIdx.x * blockDim.x + threadIdx.x;
    int stride = gridDim.x * blockDim.x;

    if (is64) {
        const long long* p = (const long long*)eraw;
        for (int e = tid; e < NE; e += stride) {
            g_row[e] = (int)p[e];
            g_col[e] = (int)p[NE + e];
        }
    } else {
        const int* p = (const int*)eraw;
        for (int e = tid; e < NE; e += stride) {
            g_row[e] = p[e];
            g_col[e] = p[NE + e];
        }
    }
    float4 z = make_float4(0.f, 0.f, 0.f, 0.f);
    float4* a = (float4*)g_agg;
    const int nvec = NN * H / 4;
    for (int i = tid; i < nvec; i += stride) a[i] = z;
}

// ---------------------------------------------------------------------------
// edge kernel: persistent, 256 thr, M-tile=128, bf16 3-term mma.sync
// msg = concat(x[src], ea) @ W1 + b1 ; red.add into g_agg[dst]
// ---------------------------------------------------------------------------
__global__ __launch_bounds__(256, 1) void edge_mma_kernel(
    const float* __restrict__ x,
    const float* __restrict__ ea,
    const float* __restrict__ W1,
    const float* __restrict__ b1)
{
    extern __shared__ __align__(16) char smem[];
    __shared__ int   s_dst[128];
    __shared__ int   s_src[128];
    __shared__ float s_b1[128];

    const int tid = threadIdx.x;
    const int lane = tid & 31;
    const int warp = tid >> 5;

    stage_B(W1, KE, smem + EB_HI, smem + EB_LO, tid, 256);
    if (tid < 128) s_b1[tid] = b1[tid];

    const uint32_t sbase = smem_u32(smem);
    const uint32_t aRowSel = (uint32_t)(lane & 15);
    const uint32_t aColSel = (uint32_t)(lane >> 4) * 16;
    const uint32_t aHiBase = sbase + EA_HI + (warp * 16 + aRowSel) * EA_STRIDE + aColSel;
    const uint32_t aLoBase = sbase + EA_LO + (warp * 16 + aRowSel) * EA_STRIDE + aColSel;
    const uint32_t bHiBase = sbase + EB_HI + aRowSel * EB_STRIDE + aColSel;
    const uint32_t bLoBase = sbase + EB_LO + aRowSel * EB_STRIDE + aColSel;

    __syncthreads();

    for (int tile = blockIdx.x; tile < EDGE_TILES; tile += gridDim.x) {
        const int e0 = tile * 128;
        if (tid < 128) {
            s_src[tid] = g_row[e0 + tid];
            s_dst[tid] = g_col[e0 + tid];
        }
        __syncthreads();

        // stage A: 128 rows x 40 float4 (gather x[src] | ea)
#pragma unroll
        for (int i = 0; i < 20; i++) {
            int idx = tid + i * 256;
            int row = idx / 40;
            int q = idx - row * 40;
            float4 v = (q < 32)
                ? ((const float4*)(x + (size_t)s_src[row] * DN))[q]
                : ((const float4*)(ea + (size_t)(e0 + row) * DE))[q - 32];
            uint32_t hi[2], lo[2];
            split4(v, hi, lo);
            *(uint2*)(smem + EA_HI + row * EA_STRIDE + q * 8) = make_uint2(hi[0], hi[1]);
            *(uint2*)(smem + EA_LO + row * EA_STRIDE + q * 8) = make_uint2(lo[0], lo[1]);
        }
        __syncthreads();

        float acc[16][4];
#pragma unroll
        for (int t = 0; t < 16; t++)
#pragma unroll
            for (int j = 0; j < 4; j++) acc[t][j] = 0.f;

        for (int ks = 0; ks < KE / 16; ks++) {
            uint32_t ah[4], al[4];
            ldsm_x4(ah, aHiBase + ks * 32);
            ldsm_x4(al, aLoBase + ks * 32);
#pragma unroll
            for (int np = 0; np < 8; np++) {
                uint32_t bh[4], bl[4];
                ldsm_x4t(bh, bHiBase + ks * 16 * EB_STRIDE + np * 32);
                ldsm_x4t(bl, bLoBase + ks * 16 * EB_STRIDE + np * 32);
                mma_bf16(acc[2 * np],     ah, bh[0], bh[1]);
                mma_bf16(acc[2 * np],     al, bh[0], bh[1]);
                mma_bf16(acc[2 * np],     ah, bl[0], bl[1]);
                mma_bf16(acc[2 * np + 1], ah, bh[2], bh[3]);
                mma_bf16(acc[2 * np + 1], al, bh[2], bh[3]);
                mma_bf16(acc[2 * np + 1], ah, bl[2], bl[3]);
            }
        }

        // epilogue: bias + red.v2 scatter
        const int r0 = warp * 16 + (lane >> 2);
        float* agg0 = g_agg + (size_t)s_dst[r0] * H;
        float* agg1 = g_agg + (size_t)s_dst[r0 + 8] * H;
#pragma unroll
        for (int nt = 0; nt < 16; nt++) {
            int col = nt * 8 + (lane & 3) * 2;
            float bb0 = s_b1[col], bb1 = s_b1[col + 1];
            red_add_v2(agg0 + col, acc[nt][0] + bb0, acc[nt][1] + bb1);
            red_add_v2(agg1 + col, acc[nt][2] + bb0, acc[nt][3] + bb1);
        }
        __syncthreads();
    }
}

// ---------------------------------------------------------------------------
// node kernel: persistent, 128 thr, M-tile=64, bf16 3-term mma.sync
// out = concat(x, agg) @ W2 + b2
// ---------------------------------------------------------------------------
__global__ __launch_bounds__(128, 1) void node_mma_kernel(
    const float* __restrict__ x,
    const float* __restrict__ W2,
    const float* __restrict__ b2,
    float* __restrict__ out)
{
    extern __shared__ __align__(16) char smem[];
    __shared__ float s_b2[128];

    const int tid = threadIdx.x;
    const int lane = tid & 31;
    const int warp = tid >> 5;

    stage_B(W2, KN, smem + NB_HI, smem + NB_LO, tid, 128);
    if (tid < 128) s_b2[tid] = b2[tid];

    const uint32_t sbase = smem_u32(smem);
    const uint32_t rowSel = (uint32_t)(lane & 15);
    const uint32_t colSel = (uint32_t)(lane >> 4) * 16;
    const uint32_t aHiBase = sbase + NA_HI + (warp * 16 + rowSel) * NA_STRIDE + colSel;
    const uint32_t aLoBase = sbase + NA_LO + (warp * 16 + rowSel) * NA_STRIDE + colSel;
    const uint32_t bHiBase = sbase + NB_HI + rowSel * EB_STRIDE + colSel;
    const uint32_t bLoBase = sbase + NB_LO + rowSel * EB_STRIDE + colSel;

    __syncthreads();

    for (int tile = blockIdx.x; tile < NODE_TILES; tile += gridDim.x) {
        const int n0 = tile * 64;

        // stage A: 64 rows x 64 float4 (concat x | agg), fully coalesced
#pragma unroll
        for (int i = 0; i < 32; i++) {
            int idx = tid + i * 128;
            int row = idx >> 6;
            int q = idx & 63;
            const int n = n0 + row;
            float4 v = (q < 32)
                ? ((const float4*)(x + (size_t)n * DN))[q]
                : ((const float4*)(g_agg + (size_t)n * H))[q - 32];
            uint32_t hi[2], lo[2];
            split4(v, hi, lo);
            *(uint2*)(smem + NA_HI + row * NA_STRIDE + q * 8) = make_uint2(hi[0], hi[1]);
            *(uint2*)(smem + NA_LO + row * NA_STRIDE + q * 8) = make_uint2(lo[0], lo[1]);
        }
        __syncthreads();

        float acc[16][4];
#pragma unroll
        for (int t = 0; t < 16; t++)
#pragma unroll
            for (int j = 0; j < 4; j++) acc[t][j] = 0.f;

        for (int ks = 0; ks < KN / 16; ks++) {
            uint32_t ah[4], al[4];
            ldsm_x4(ah, aHiBase + ks * 32);
            ldsm_x4(al, aLoBase + ks * 32);
#pragma unroll
            for (int np = 0; np < 8; np++) {
                uint32_t bh[4], bl[4];
                ldsm_x4t(bh, bHiBase + ks * 16 * EB_STRIDE + np * 32);
                ldsm_x4t(bl, bLoBase + ks * 16 * EB_STRIDE + np * 32);
                mma_bf16(acc[2 * np],     ah, bh[0], bh[1]);
                mma_bf16(acc[2 * np],     al, bh[0], bh[1]);
                mma_bf16(acc[2 * np],     ah, bl[0], bl[1]);
                mma_bf16(acc[2 * np + 1], ah, bh[2], bh[3]);
                mma_bf16(acc[2 * np + 1], al, bh[2], bh[3]);
                mma_bf16(acc[2 * np + 1], ah, bl[2], bl[3]);
            }
        }

        // epilogue: bias + store
        const int r0 = warp * 16 + (lane >> 2);
        float* o0 = out + (size_t)(n0 + r0) * H;
        float* o1 = out + (size_t)(n0 + r0 + 8) * H;
#pragma unroll
        for (int nt = 0; nt < 16; nt++) {
            int col = nt * 8 + (lane & 3) * 2;
            float bb0 = s_b2[col], bb1 = s_b2[col + 1];
            *(float2*)(o0 + col) = make_float2(acc[nt][0] + bb0, acc[nt][1] + bb1);
            *(float2*)(o1 + col) = make_float2(acc[nt][2] + bb0, acc[nt][3] + bb1);
        }
        __syncthreads();
    }
}

// ---------------------------------------------------------------------------
// inputs: 0=x 1=edge_index 2=edge_attr 3=u 4=batch 5=W1 6=b1 7=W2 8=b2
// ---------------------------------------------------------------------------
extern "C" void kernel_launch(void* const* d_in, const int* in_sizes, int n_in,
                              void* d_out, int out_size)
{
    const float*        x    = (const float*)d_in[0];
    const unsigned int* eraw = (const unsigned int*)d_in[1];
    const float*        ea   = (const float*)d_in[2];
    const float*        W1   = (const float*)d_in[5];
    const float*        b1   = (const float*)d_in[6];
    const float*        W2   = (const float*)d_in[7];
    const float*        b2   = (const float*)d_in[8];

    cudaFuncSetAttribute(edge_mma_kernel,
                         cudaFuncAttributeMaxDynamicSharedMemorySize, EDGE_SMEM);
    cudaFuncSetAttribute(node_mma_kernel,
                         cudaFuncAttributeMaxDynamicSharedMemorySize, NODE_SMEM);

    prep_kernel<<<2048, 256>>>(eraw);
    edge_mma_kernel<<<NSM, 256, EDGE_SMEM>>>(x, ea, W1, b1);
    node_mma_kernel<<<NSM, 128, NODE_SMEM>>>(x, W2, b2, (float*)d_out);
}

// round 7
// speedup vs baseline: 2.0499x; 1.2456x over previous
#include <cuda_runtime.h>
#include <cuda_bf16.h>
#include <cstdint>

#define NN 200000
#define NE 640000
#define DN 128
#define DE 32
#define H  128
#define KE 160      // edge K
#define KN 256      // node K
#define NSM 148

// ---------------- edge kernel v2 (weights-as-A, 2 CTA/SM) ------------------
#define ETILE 64
#define EDGE_TILES2 (NE / ETILE)        // 10000
#define EGRID (2 * NSM)                 // 296

#define WA_STRIDE 336                   // W A-layout rows [h][k] bf16 + pad
#define EH_STRIDE 336                   // edge rows [e][k] bf16 + pad
#define OUT_STRIDE 528                  // transpose buffer rows [e][h] fp32 + pad

#define WLO_OFF 0
#define EHI_OFF (128 * WA_STRIDE)               // 43008
#define ELO_OFF (EHI_OFF + ETILE * EH_STRIDE)   // 64512
#define OUT_OFF EHI_OFF                          // overlay (33792 <= 43008)
#define EDGE2_SMEM (ELO_OFF + ETILE * EH_STRIDE) // 86016

// ---------------- node kernel (unchanged from R4) --------------------------
#define NODE_TILES (NN / 64)    // 3125
#define EB_STRIDE 272
#define NA_STRIDE 528
#define NA_HI 0
#define NA_LO (64 * NA_STRIDE)
#define NB_HI (2 * 64 * NA_STRIDE)
#define NB_LO (NB_HI + KN * EB_STRIDE)
#define NODE_SMEM (NB_LO + KN * EB_STRIDE)

__device__ __align__(256) float g_agg[(size_t)NN * H];
__device__ int g_row[NE];
__device__ int g_col[NE];

// ---------------------------------------------------------------------------
// helpers
// ---------------------------------------------------------------------------
__device__ __forceinline__ uint32_t smem_u32(const void* p) {
    uint32_t a;
    asm("{ .reg .u64 t; cvta.to.shared.u64 t, %1; cvt.u32.u64 %0, t; }"
        : "=r"(a) : "l"(p));
    return a;
}
__device__ __forceinline__ uint32_t pack_bf16(float v0, float v1) {
    uint32_t r;
    asm("cvt.rn.bf16x2.f32 %0, %1, %2;" : "=r"(r) : "f"(v1), "f"(v0));
    return r;
}
__device__ __forceinline__ void split4(float4 v, uint32_t* hi, uint32_t* lo) {
    uint32_t h01 = pack_bf16(v.x, v.y);
    uint32_t h23 = pack_bf16(v.z, v.w);
    float r0 = v.x - __uint_as_float(h01 << 16);
    float r1 = v.y - __uint_as_float(h01 & 0xFFFF0000u);
    float r2 = v.z - __uint_as_float(h23 << 16);
    float r3 = v.w - __uint_as_float(h23 & 0xFFFF0000u);
    hi[0] = h01; hi[1] = h23;
    lo[0] = pack_bf16(r0, r1);
    lo[1] = pack_bf16(r2, r3);
}
__device__ __forceinline__ void ldsm_x4(uint32_t* r, uint32_t a) {
    asm volatile("ldmatrix.sync.aligned.m8n8.x4.shared.b16 {%0,%1,%2,%3}, [%4];"
                 : "=r"(r[0]), "=r"(r[1]), "=r"(r[2]), "=r"(r[3]) : "r"(a));
}
__device__ __forceinline__ void ldsm_x4t(uint32_t* r, uint32_t a) {
    asm volatile("ldmatrix.sync.aligned.m8n8.x4.trans.shared.b16 {%0,%1,%2,%3}, [%4];"
                 : "=r"(r[0]), "=r"(r[1]), "=r"(r[2]), "=r"(r[3]) : "r"(a));
}
__device__ __forceinline__ void mma_bf16(float* c, const uint32_t* a,
                                         uint32_t b0, uint32_t b1) {
    asm volatile(
        "mma.sync.aligned.m16n8k16.row.col.f32.bf16.bf16.f32 "
        "{%0,%1,%2,%3}, {%4,%5,%6,%7}, {%8,%9}, {%0,%1,%2,%3};"
        : "+f"(c[0]), "+f"(c[1]), "+f"(c[2]), "+f"(c[3])
        : "r"(a[0]), "r"(a[1]), "r"(a[2]), "r"(a[3]), "r"(b0), "r"(b1));
}
// proven on this box in R4's passing kernel
__device__ __forceinline__ void red_add_v2(float* p, float a, float b) {
    asm volatile("red.global.add.v2.f32 [%0], {%1,%2};"
                 :: "l"(p), "f"(a), "f"(b) : "memory");
}

// ---------------------------------------------------------------------------
// prep: detect int64 vs int32 edge_index, normalize, zero agg
// ---------------------------------------------------------------------------
__global__ void prep_kernel(const unsigned int* __restrict__ eraw)
{
    bool is64 = true;
    for (int i = 1; i < 64; i += 2)
        if (eraw[i] != 0u) { is64 = false; break; }

    int tid = blockIdx.x * blockDim.x + threadIdx.x;
    int stride = gridDim.x * blockDim.x;

    if (is64) {
        const long long* p = (const long long*)eraw;
        for (int e = tid; e < NE; e += stride) {
            g_row[e] = (int)p[e];
            g_col[e] = (int)p[NE + e];
        }
    } else {
        const int* p = (const int*)eraw;
        for (int e = tid; e < NE; e += stride) {
            g_row[e] = p[e];
            g_col[e] = p[NE + e];
        }
    }
    float4 z = make_float4(0.f, 0.f, 0.f, 0.f);
    float4* a = (float4*)g_agg;
    const int nvec = NN * H / 4;
    for (int i = tid; i < nvec; i += stride) a[i] = z;
}

// ---------------------------------------------------------------------------
// edge kernel v2: weights-as-A in registers, edges-as-B ldsm (non-trans),
// 2 CTA/SM, transpose epilogue -> red.v2 scatter.
// Warp w owns H rows [16w, 16w+16); tile = 64 edges.
// D^T[h][e] = sum_k W1[k][h] * in[e][k]  (3-term bf16 split)
// ---------------------------------------------------------------------------
__global__ __launch_bounds__(256, 2) void edge_mma_kernel(
    const float* __restrict__ x,
    const float* __restrict__ ea,
    const float* __restrict__ W1,
    const float* __restrict__ b1)
{
    extern __shared__ __align__(16) char smem[];
    __shared__ int s_dst[ETILE];

    const int tid = threadIdx.x;
    const int lane = tid & 31;
    const int warp = tid >> 5;

    // ---- stage W-hi into wbuf (offset 0), load frags to regs ----
    for (int idx = tid; idx < 128 * KE; idx += 256) {
        int h = idx / KE, k = idx - h * KE;
        float v = W1[k * 128 + h];
        *(__nv_bfloat16*)(smem + WLO_OFF + h * WA_STRIDE + k * 2) =
            __float2bfloat16_rn(v);
    }
    __syncthreads();

    const uint32_t sbase = smem_u32(smem);
    const uint32_t wA_addr = sbase + WLO_OFF
        + (warp * 16 + (lane & 15)) * WA_STRIDE + ((lane >> 4) & 1) * 16;

    uint32_t whi[10][4];
#pragma unroll
    for (int ks = 0; ks < 10; ks++) ldsm_x4(whi[ks], wA_addr + ks * 32);
    __syncthreads();

    // ---- overwrite wbuf with W-lo (residuals) ----
    for (int idx = tid; idx < 128 * KE; idx += 256) {
        int h = idx / KE, k = idx - h * KE;
        float v = W1[k * 128 + h];
        float r = v - __bfloat162float(__float2bfloat16_rn(v));
        *(__nv_bfloat16*)(smem + WLO_OFF + h * WA_STRIDE + k * 2) =
            __float2bfloat16_rn(r);
    }

    // per-thread bias values (h0 = 16w + lane/4, h1 = h0+8)
    const int h0 = warp * 16 + (lane >> 2);
    const float bia0 = b1[h0];
    const float bia1 = b1[h0 + 8];

    // B-operand ldsm address (lane part): matrices (n0-7,k0-7),(n0-7,k8-15),
    // (n8-15,k0-7),(n8-15,k8-15)
    const uint32_t rowsel = ((lane >> 4) & 1) * 8 + (lane & 7);
    const uint32_t col16 = ((lane >> 3) & 1) * 16;
    const uint32_t ehB = sbase + EHI_OFF + rowsel * EH_STRIDE + col16;
    const uint32_t elB = sbase + ELO_OFF + rowsel * EH_STRIDE + col16;

    for (int tile = blockIdx.x; tile < EDGE_TILES2; tile += gridDim.x) {
        const int e0 = tile * ETILE;

        __syncthreads();   // previous scatter done -> buffers reusable
                           // (also orders W-lo writes before first ldsm)

        if (tid < ETILE) s_dst[tid] = g_col[e0 + tid];

        // ---- stage 64 edge rows (gather x[src] | ea), split hi/lo ----
#pragma unroll
        for (int i = 0; i < 10; i++) {
            int idx = tid + i * 256;        // < 2560
            int row = idx / 40;
            int q = idx - row * 40;
            int src = g_row[e0 + row];
            float4 v = (q < 32)
                ? ((const float4*)(x + (size_t)src * DN))[q]
                : ((const float4*)(ea + (size_t)(e0 + row) * DE))[q - 32];
            uint32_t hi[2], lo[2];
            split4(v, hi, lo);
            *(uint2*)(smem + EHI_OFF + row * EH_STRIDE + q * 8) =
                make_uint2(hi[0], hi[1]);
            *(uint2*)(smem + ELO_OFF + row * EH_STRIDE + q * 8) =
                make_uint2(lo[0], lo[1]);
        }
        __syncthreads();

        // ---- mma mainloop ----
        float acc[8][4];
#pragma unroll
        for (int t = 0; t < 8; t++)
#pragma unroll
            for (int j = 0; j < 4; j++) acc[t][j] = 0.f;

#pragma unroll
        for (int ks = 0; ks < 10; ks++) {
            uint32_t wlo[4];
            ldsm_x4(wlo, wA_addr + ks * 32);
#pragma unroll
            for (int g = 0; g < 4; g++) {
                uint32_t bh[4], bl[4];
                ldsm_x4(bh, ehB + g * (16 * EH_STRIDE) + ks * 32);
                ldsm_x4(bl, elB + g * (16 * EH_STRIDE) + ks * 32);
                mma_bf16(acc[2 * g],     whi[ks], bh[0], bh[1]);
                mma_bf16(acc[2 * g],     wlo,     bh[0], bh[1]);
                mma_bf16(acc[2 * g],     whi[ks], bl[0], bl[1]);
                mma_bf16(acc[2 * g + 1], whi[ks], bh[2], bh[3]);
                mma_bf16(acc[2 * g + 1], wlo,     bh[2], bh[3]);
                mma_bf16(acc[2 * g + 1], whi[ks], bl[2], bl[3]);
            }
        }
        __syncthreads();   // all reads of edge buffers done

        // ---- transpose D^T -> [e][h] fp32 in smem (overlay), add bias ----
        {
            char* ob = smem + OUT_OFF;
            const int eb = 2 * (lane & 3);
#pragma unroll
            for (int nt = 0; nt < 8; nt++) {
                char* p = ob + (nt * 8 + eb) * OUT_STRIDE + h0 * 4;
                *(float*)(p)                   = acc[nt][0] + bia0;
                *(float*)(p + OUT_STRIDE)      = acc[nt][1] + bia0;
                *(float*)(p + 32)              = acc[nt][2] + bia1;
                *(float*)(p + OUT_STRIDE + 32) = acc[nt][3] + bia1;
            }
        }
        __syncthreads();

        // ---- scatter: red.v2 into g_agg[dst] ----
        {
            const int e = tid & 63;
            const int ch = tid >> 6;        // 0..3, 32 h each
            const float* src =
                (const float*)(smem + OUT_OFF + e * OUT_STRIDE + ch * 128);
            float* dp = g_agg + (size_t)s_dst[e] * H + ch * 32;
#pragma unroll
            for (int c = 0; c < 16; c++) {
                float2 v = *(const float2*)(src + c * 2);
                red_add_v2(dp + c * 2, v.x, v.y);
            }
        }
    }
}

// ---------------------------------------------------------------------------
// node kernel: persistent, 128 thr, M-tile=64, bf16 3-term mma.sync (R4)
// ---------------------------------------------------------------------------
__device__ __forceinline__ void stage_B(const float* __restrict__ W, int K,
                                        char* bhi, char* blo, int tid, int nthr) {
    for (int idx = tid; idx < K * 128; idx += nthr) {
        int k = idx >> 7, n = idx & 127;
        float v = W[idx];
        __nv_bfloat16 h = __float2bfloat16_rn(v);
        float r = v - __bfloat162float(h);
        *(__nv_bfloat16*)(bhi + k * EB_STRIDE + n * 2) = h;
        *(__nv_bfloat16*)(blo + k * EB_STRIDE + n * 2) = __float2bfloat16_rn(r);
    }
}

__global__ __launch_bounds__(128, 1) void node_mma_kernel(
    const float* __restrict__ x,
    const float* __restrict__ W2,
    const float* __restrict__ b2,
    float* __restrict__ out)
{
    extern __shared__ __align__(16) char smem[];
    __shared__ float s_b2[128];

    const int tid = threadIdx.x;
    const int lane = tid & 31;
    const int warp = tid >> 5;

    stage_B(W2, KN, smem + NB_HI, smem + NB_LO, tid, 128);
    if (tid < 128) s_b2[tid] = b2[tid];

    const uint32_t sbase = smem_u32(smem);
    const uint32_t rowSel = (uint32_t)(lane & 15);
    const uint32_t colSel = (uint32_t)(lane >> 4) * 16;
    const uint32_t aHiBase = sbase + NA_HI + (warp * 16 + rowSel) * NA_STRIDE + colSel;
    const uint32_t aLoBase = sbase + NA_LO + (warp * 16 + rowSel) * NA_STRIDE + colSel;
    const uint32_t bHiBase = sbase + NB_HI + rowSel * EB_STRIDE + colSel;
    const uint32_t bLoBase = sbase + NB_LO + rowSel * EB_STRIDE + colSel;

    __syncthreads();

    for (int tile = blockIdx.x; tile < NODE_TILES; tile += gridDim.x) {
        const int n0 = tile * 64;

#pragma unroll
        for (int i = 0; i < 32; i++) {
            int idx = tid + i * 128;
            int row = idx >> 6;
            int q = idx & 63;
            const int n = n0 + row;
            float4 v = (q < 32)
                ? ((const float4*)(x + (size_t)n * DN))[q]
                : ((const float4*)(g_agg + (size_t)n * H))[q - 32];
            uint32_t hi[2], lo[2];
            split4(v, hi, lo);
            *(uint2*)(smem + NA_HI + row * NA_STRIDE + q * 8) = make_uint2(hi[0], hi[1]);
            *(uint2*)(smem + NA_LO + row * NA_STRIDE + q * 8) = make_uint2(lo[0], lo[1]);
        }
        __syncthreads();

        float acc[16][4];
#pragma unroll
        for (int t = 0; t < 16; t++)
#pragma unroll
            for (int j = 0; j < 4; j++) acc[t][j] = 0.f;

        for (int ks = 0; ks < KN / 16; ks++) {
            uint32_t ah[4], al[4];
            ldsm_x4(ah, aHiBase + ks * 32);
            ldsm_x4(al, aLoBase + ks * 32);
#pragma unroll
            for (int np = 0; np < 8; np++) {
                uint32_t bh[4], bl[4];
                ldsm_x4t(bh, bHiBase + ks * 16 * EB_STRIDE + np * 32);
                ldsm_x4t(bl, bLoBase + ks * 16 * EB_STRIDE + np * 32);
                mma_bf16(acc[2 * np],     ah, bh[0], bh[1]);
                mma_bf16(acc[2 * np],     al, bh[0], bh[1]);
                mma_bf16(acc[2 * np],     ah, bl[0], bl[1]);
                mma_bf16(acc[2 * np + 1], ah, bh[2], bh[3]);
                mma_bf16(acc[2 * np + 1], al, bh[2], bh[3]);
                mma_bf16(acc[2 * np + 1], ah, bl[2], bl[3]);
            }
        }

        const int r0 = warp * 16 + (lane >> 2);
        float* o0 = out + (size_t)(n0 + r0) * H;
        float* o1 = out + (size_t)(n0 + r0 + 8) * H;
#pragma unroll
        for (int nt = 0; nt < 16; nt++) {
            int col = nt * 8 + (lane & 3) * 2;
            float bb0 = s_b2[col], bb1 = s_b2[col + 1];
            *(float2*)(o0 + col) = make_float2(acc[nt][0] + bb0, acc[nt][1] + bb1);
            *(float2*)(o1 + col) = make_float2(acc[nt][2] + bb0, acc[nt][3] + bb1);
        }
        __syncthreads();
    }
}

// ---------------------------------------------------------------------------
// inputs: 0=x 1=edge_index 2=edge_attr 3=u 4=batch 5=W1 6=b1 7=W2 8=b2
// ---------------------------------------------------------------------------
extern "C" void kernel_launch(void* const* d_in, const int* in_sizes, int n_in,
                              void* d_out, int out_size)
{
    const float*        x    = (const float*)d_in[0];
    const unsigned int* eraw = (const unsigned int*)d_in[1];
    const float*        ea   = (const float*)d_in[2];
    const float*        W1   = (const float*)d_in[5];
    const float*        b1   = (const float*)d_in[6];
    const float*        W2   = (const float*)d_in[7];
    const float*        b2   = (const float*)d_in[8];

    cudaFuncSetAttribute(edge_mma_kernel,
                         cudaFuncAttributeMaxDynamicSharedMemorySize, EDGE2_SMEM);
    cudaFuncSetAttribute(node_mma_kernel,
                         cudaFuncAttributeMaxDynamicSharedMemorySize, NODE_SMEM);

    prep_kernel<<<2048, 256>>>(eraw);
    edge_mma_kernel<<<EGRID, 256, EDGE2_SMEM>>>(x, ea, W1, b1);
    node_mma_kernel<<<NSM, 128, NODE_SMEM>>>(x, W2, b2, (float*)d_out);
}